// round 7
// baseline (speedup 1.0000x reference)
#include <cuda_runtime.h>

#define MAXDISP 192
#define HH      192
#define WW      384
#define WD      (WW + MAXDISP - 1)   /* 575 */
#define HW      (HH * WW)            /* 73728 */

#define NCHUNK 4                     /* D-chunks per view (warps = view x chunk) */
#define DPC    (MAXDISP / NCHUNK)    /* 48 disparities per chunk */
#define PIX    32                    /* pixels per tile */
#define TILES  2                     /* tiles per block -> single-wave grid */

// v layout: [1][4][D][H][WD]  ch 0 = logits, ch 1..3 = color
// out layout: color_1[3*HW] | color_2[3*HW] | disp_1[HW] | disp_2[HW]

__global__ __launch_bounds__(256, 8)
void volume_render_v4_kernel(const float* __restrict__ v, float* __restrict__ out) {
    const int lane  = threadIdx.x & 31;
    const int warp  = threadIdx.x >> 5;
    const int view  = warp & 1;          // 0: col=w, 1: col=w+shift
    const int chunk = warp >> 1;         // 0..3

    const int stride_d = HH * WD;            // 110400
    const int stride_c = MAXDISP * HH * WD;  // 21196800

    const int d0   = chunk * DPC;
    const int sh0  = view ? (MAXDISP - 1 - d0) : 0;
    const int step = stride_d - view;        // view2 shift shrinks by 1 per d
    const float dv0 = (float)(MAXDISP - 1 - d0);

    __shared__ float red[2 * NCHUNK][5][PIX];
    __shared__ float fin[2][5][PIX];

    // output mapping (outv 0-2: color_1 ; 3-5: color_2 ; 6: disp_1 ; 7: disp_2)
    const int outv = threadIdx.x >> 5;
    const int opx  = threadIdx.x & 31;
    const int ovw  = (outv < 3) ? 0 : (outv < 6 ? 1 : (outv - 6));
    const int oval = (outv < 6) ? (2 + outv - ovw * 3) : 1;

    #pragma unroll 1
    for (int t = 0; t < TILES; ++t) {
        const int pix0 = (blockIdx.x * TILES + t) * PIX;
        const int h    = pix0 / WW;
        const int w0   = pix0 % WW;

        const float* __restrict__ p = v + d0 * stride_d + h * WD + w0 + lane + sh0;

        float l = 0.f, ad = 0.f, ac0 = 0.f, ac1 = 0.f, ac2 = 0.f;
        float dv = dv0;

        #pragma unroll 4
        for (int i = 0; i < DPC; ++i) {
            // 4 independent coalesced loads
            const float b  = p[0];
            const float q0 = p[stride_c];
            const float q1 = p[2 * stride_c];
            const float q2 = p[3 * stride_c];

            // no max-subtraction: logits ~ N(0,1); exp cannot overflow fp32 and
            // the softmax ratio is shift-invariant; partials are linear.
            const float e = __expf(b);

            l   += e;
            ad   = fmaf(e, dv, ad);
            ac0  = fmaf(e, q0, ac0);
            ac1  = fmaf(e, q1, ac1);
            ac2  = fmaf(e, q2, ac2);

            p  += step;
            dv -= 1.0f;
        }

        red[warp][0][lane] = l;
        red[warp][1][lane] = ad;
        red[warp][2][lane] = ac0;
        red[warp][3][lane] = ac1;
        red[warp][4][lane] = ac2;
        __syncthreads();

        // reduce over chunks: fin[view][val][px], 320 tasks over 256 threads
        for (int tt = threadIdx.x; tt < 2 * 5 * PIX; tt += 256) {
            const int vw  = tt / (5 * PIX);
            const int val = (tt / PIX) % 5;
            const int px  = tt & 31;
            float s = 0.f;
            #pragma unroll
            for (int cc = 0; cc < NCHUNK; ++cc) s += red[cc * 2 + vw][val][px];
            fin[vw][val][px] = s;
        }
        __syncthreads();

        // 8 outputs x 32 px = 256 tasks, one per thread
        const float a = fin[ovw][oval][opx];
        const float s = fin[ovw][0][opx];
        out[outv * HW + pix0 + opx] = a / s;

        if (t + 1 < TILES) __syncthreads();   // protect smem reuse
    }
}

extern "C" void kernel_launch(void* const* d_in, const int* in_sizes, int n_in,
                              void* d_out, int out_size) {
    const float* v = (const float*)d_in[0];
    float* out = (float*)d_out;

    const int blocks = HW / (PIX * TILES);   // 1152 -> single wave at 8 blocks/SM
    volume_render_v4_kernel<<<blocks, 256>>>(v, out);
}